// round 2
// baseline (speedup 1.0000x reference)
#include <cuda_runtime.h>
#include <math.h>

#define N_NODES 100000
#define HDIM    64
#define CDIM    16
#define NPB     256   // nodes per block (node kernel)
#define TPB     256   // threads per block (node kernel)

// -------- scratch (no allocs allowed -> __device__ globals) --------
__device__ float g_S0[(size_t)N_NODES * HDIM];  // sum of feats over type-true edges per dst
__device__ float g_S1[(size_t)N_NODES * HDIM];  // type-false
__device__ float g_c0[N_NODES];                 // count of type-true edges per dst
__device__ float g_c1[N_NODES];                 // count of type-false
__device__ int   g_et_is_i32;                   // edge_types dtype flag (1 = int32, 0 = uint8)

// =====================================================================
// Detect edge_types dtype. bool-as-uint8: ~50% of bytes are 1.
// bool-as-int32 (LE): only every 4th byte can be 1 (~12.5%).
// Pure function of input -> deterministic; plain write -> replay-safe.
// =====================================================================
__global__ void detect_et_kernel(const unsigned char* __restrict__ et, int E)
{
    __shared__ int cnt;
    if (threadIdx.x == 0) cnt = 0;
    __syncthreads();
    int K = 4096 < E ? 4096 : E;
    int local = 0;
    for (int i = threadIdx.x; i < K; i += blockDim.x)
        local += (et[i] != 0);
    atomicAdd(&cnt, local);
    __syncthreads();
    if (threadIdx.x == 0)
        g_et_is_i32 = (cnt < K / 4) ? 1 : 0;
}

// =====================================================================
// Scatter: S_t[dst] += features[src], c_t[dst] += 1. 16 threads/edge,
// float4 vector atomics (sm_90+).
// =====================================================================
__global__ void __launch_bounds__(256) scatter_kernel(
    const float* __restrict__ feat,
    const int*   __restrict__ src,
    const int*   __restrict__ dst,
    const void*  __restrict__ et,
    int E)
{
    int gtid = blockIdx.x * blockDim.x + threadIdx.x;
    int e = gtid >> 4;
    if (e >= E) return;
    int l = gtid & 15;

    int s = __ldg(src + e);
    int d = __ldg(dst + e);
    bool t;
    if (g_et_is_i32)
        t = __ldg((const int*)et + e) != 0;
    else
        t = __ldg((const unsigned char*)et + e) != 0;

    float4 v = __ldg((const float4*)(feat + (size_t)s * HDIM) + l);
    float* Sx = t ? g_S0 : g_S1;
    atomicAdd(((float4*)(Sx + (size_t)d * HDIM)) + l, v);
    if (l == 0) atomicAdd(t ? (g_c0 + d) : (g_c1 + d), 1.0f);
}

// =====================================================================
// Fused node kernel: agg = S0@W0^T + c0*b0 + S1@W1^T + c1*b1;
// GRU(agg, feat); out = h@Wout^T + bout. One thread per node.
// Shared: sF[256][65], sX[256][65] (staging/agg/h), sW (8192 f, k-major
// weight slices), sB (528 biases). Row-private compute, conflict-free pad.
// =====================================================================
__device__ __forceinline__ void loadW2(float* sW, const float* __restrict__ A,
                                       const float* __restrict__ B, int row0, int tid)
{
    for (int i = tid; i < 4096; i += TPB) {
        int m = i >> 6, k = i & 63;
        sW[k * 64 + m]        = A[(row0 + m) * 64 + k];
        sW[4096 + k * 64 + m] = B[(row0 + m) * 64 + k];
    }
}

__device__ __forceinline__ float sigmoidf_fast(float x)
{
    return __fdividef(1.0f, 1.0f + __expf(-x));
}

__global__ void __launch_bounds__(TPB, 1) node_kernel(
    const float* __restrict__ feat,
    const float* __restrict__ W0,  const float* __restrict__ b0,
    const float* __restrict__ W1,  const float* __restrict__ b1,
    const float* __restrict__ Wih, const float* __restrict__ Whh,
    const float* __restrict__ bih, const float* __restrict__ bhh,
    const float* __restrict__ Wout,const float* __restrict__ bout,
    float* __restrict__ out, int Nn)
{
    extern __shared__ float smem[];
    float* sF = smem;            // 256*65 = 16640
    float* sX = smem + 16640;    // 16640
    float* sW = smem + 33280;    // 8192
    float* sB = smem + 41472;    // 528

    const int tid  = threadIdx.x;
    const int n0   = blockIdx.x * NPB;
    const int n    = n0 + tid;
    const int trow = tid * 65;

    // biases: [0:64) b0 | [64:128) b1 | [128:320) bih | [320:512) bhh | [512:528) bout
    for (int i = tid; i < 528; i += TPB) {
        float v;
        if (i < 64)       v = b0[i];
        else if (i < 128) v = b1[i - 64];
        else if (i < 320) v = bih[i - 128];
        else if (i < 512) v = bhh[i - 320];
        else              v = bout[i - 512];
        sB[i] = v;
    }
    // stage features and S0 tiles; load W0|W1 k-major
    for (int i = tid; i < NPB * 64; i += TPB) {
        int r = i >> 6, c = i & 63;
        int nn = n0 + r;
        sF[r * 65 + c] = (nn < Nn) ? feat[(size_t)nn * 64 + c] : 0.f;
        sX[r * 65 + c] = (nn < Nn) ? g_S0[(size_t)nn * 64 + c] : 0.f;
    }
    for (int i = tid; i < 4096; i += TPB) {
        int m = i >> 6, k = i & 63;
        sW[k * 64 + m]        = W0[m * 64 + k];
        sW[4096 + k * 64 + m] = W1[m * 64 + k];
    }
    __syncthreads();

    // ---- phase A: agg ----
    float acc[64];
    {
        float c0n = (n < Nn) ? g_c0[n] : 0.f;
        float c1n = (n < Nn) ? g_c1[n] : 0.f;
        #pragma unroll
        for (int m = 0; m < 64; m++) acc[m] = c0n * sB[m] + c1n * sB[64 + m];
    }
    #pragma unroll 4
    for (int k = 0; k < 64; k++) {
        float x = sX[trow + k];
        const float4* w4 = (const float4*)(sW + k * 64);
        #pragma unroll
        for (int m4 = 0; m4 < 16; m4++) {
            float4 w = w4[m4];
            acc[4*m4+0] += x * w.x; acc[4*m4+1] += x * w.y;
            acc[4*m4+2] += x * w.z; acc[4*m4+3] += x * w.w;
        }
    }
    __syncthreads();
    for (int i = tid; i < NPB * 64; i += TPB) {
        int r = i >> 6, c = i & 63;
        int nn = n0 + r;
        sX[r * 65 + c] = (nn < Nn) ? g_S1[(size_t)nn * 64 + c] : 0.f;
    }
    __syncthreads();
    #pragma unroll 4
    for (int k = 0; k < 64; k++) {
        float x = sX[trow + k];
        const float4* w4 = (const float4*)(sW + 4096 + k * 64);
        #pragma unroll
        for (int m4 = 0; m4 < 16; m4++) {
            float4 w = w4[m4];
            acc[4*m4+0] += x * w.x; acc[4*m4+1] += x * w.y;
            acc[4*m4+2] += x * w.z; acc[4*m4+3] += x * w.w;
        }
    }
    __syncthreads();
    // park agg in own row of sX (row-private, no sync hazard)
    #pragma unroll
    for (int m = 0; m < 64; m++) sX[trow + m] = acc[m];

    // ---- r gate ----
    loadW2(sW, Wih, Whh, 0, tid);
    __syncthreads();
    float rg[64];
    #pragma unroll
    for (int m = 0; m < 64; m++) rg[m] = sB[128 + m] + sB[320 + m];
    #pragma unroll 2
    for (int k = 0; k < 64; k++) {
        float ag = sX[trow + k], f = sF[trow + k];
        const float4* wa = (const float4*)(sW + k * 64);
        const float4* wb = (const float4*)(sW + 4096 + k * 64);
        #pragma unroll
        for (int m4 = 0; m4 < 16; m4++) {
            float4 a4 = wa[m4], b4 = wb[m4];
            rg[4*m4+0] += ag * a4.x + f * b4.x;
            rg[4*m4+1] += ag * a4.y + f * b4.y;
            rg[4*m4+2] += ag * a4.z + f * b4.z;
            rg[4*m4+3] += ag * a4.w + f * b4.w;
        }
    }
    #pragma unroll
    for (int m = 0; m < 64; m++) rg[m] = sigmoidf_fast(rg[m]);

    // ---- n gate: nacc = i_n + r * h_n (r already known -> single accumulator) ----
    __syncthreads();
    loadW2(sW, Wih, Whh, 128, tid);
    __syncthreads();
    float nv[64];
    #pragma unroll
    for (int m = 0; m < 64; m++) nv[m] = sB[256 + m] + rg[m] * sB[448 + m];
    #pragma unroll 2
    for (int k = 0; k < 64; k++) {
        float ag = sX[trow + k], f = sF[trow + k];
        const float4* wa = (const float4*)(sW + k * 64);
        const float4* wb = (const float4*)(sW + 4096 + k * 64);
        #pragma unroll
        for (int m4 = 0; m4 < 16; m4++) {
            float4 a4 = wa[m4], b4 = wb[m4];
            nv[4*m4+0] += ag * a4.x + (f * b4.x) * rg[4*m4+0];
            nv[4*m4+1] += ag * a4.y + (f * b4.y) * rg[4*m4+1];
            nv[4*m4+2] += ag * a4.z + (f * b4.z) * rg[4*m4+2];
            nv[4*m4+3] += ag * a4.w + (f * b4.w) * rg[4*m4+3];
        }
    }
    #pragma unroll
    for (int m = 0; m < 64; m++) nv[m] = tanhf(nv[m]);

    // ---- z gate + h ----
    __syncthreads();
    loadW2(sW, Wih, Whh, 64, tid);
    __syncthreads();
    float zg[64];
    #pragma unroll
    for (int m = 0; m < 64; m++) zg[m] = sB[192 + m] + sB[384 + m];
    #pragma unroll 2
    for (int k = 0; k < 64; k++) {
        float ag = sX[trow + k], f = sF[trow + k];
        const float4* wa = (const float4*)(sW + k * 64);
        const float4* wb = (const float4*)(sW + 4096 + k * 64);
        #pragma unroll
        for (int m4 = 0; m4 < 16; m4++) {
            float4 a4 = wa[m4], b4 = wb[m4];
            zg[4*m4+0] += ag * a4.x + f * b4.x;
            zg[4*m4+1] += ag * a4.y + f * b4.y;
            zg[4*m4+2] += ag * a4.z + f * b4.z;
            zg[4*m4+3] += ag * a4.w + f * b4.w;
        }
    }
    #pragma unroll
    for (int m = 0; m < 64; m++) {
        float z = sigmoidf_fast(zg[m]);
        float h = (1.0f - z) * nv[m] + z * sF[trow + m];
        sX[trow + m] = h;   // park h (agg dead), row-private
    }

    // ---- classifier ----
    __syncthreads();
    for (int i = tid; i < 1024; i += TPB) {
        int c = i >> 6, k = i & 63;
        sW[k * 16 + c] = Wout[c * 64 + k];
    }
    __syncthreads();
    float o[16];
    #pragma unroll
    for (int c = 0; c < 16; c++) o[c] = sB[512 + c];
    #pragma unroll 4
    for (int k = 0; k < 64; k++) {
        float hv = sX[trow + k];
        const float4* w = (const float4*)(sW + k * 16);
        #pragma unroll
        for (int c4 = 0; c4 < 4; c4++) {
            float4 ww = w[c4];
            o[4*c4+0] += hv * ww.x; o[4*c4+1] += hv * ww.y;
            o[4*c4+2] += hv * ww.z; o[4*c4+3] += hv * ww.w;
        }
    }
    if (n < Nn) {
        float4* po = (float4*)(out + (size_t)n * 16);
        po[0] = make_float4(o[0],  o[1],  o[2],  o[3]);
        po[1] = make_float4(o[4],  o[5],  o[6],  o[7]);
        po[2] = make_float4(o[8],  o[9],  o[10], o[11]);
        po[3] = make_float4(o[12], o[13], o[14], o[15]);
    }
}

// =====================================================================
extern "C" void kernel_launch(void* const* d_in, const int* in_sizes, int n_in,
                              void* d_out, int out_size)
{
    const float* feat = (const float*)d_in[0];
    const int*   src  = (const int*)d_in[1];
    const int*   dst  = (const int*)d_in[2];
    const void*  et   = d_in[3];
    const float* W0   = (const float*)d_in[4];
    const float* b0   = (const float*)d_in[5];
    const float* W1   = (const float*)d_in[6];
    const float* b1   = (const float*)d_in[7];
    const float* Wih  = (const float*)d_in[8];
    const float* Whh  = (const float*)d_in[9];
    const float* bih  = (const float*)d_in[10];
    const float* bhh  = (const float*)d_in[11];
    const float* Wout = (const float*)d_in[12];
    const float* bout = (const float*)d_in[13];
    float* out = (float*)d_out;

    const int E = in_sizes[1];
    const int Nn = in_sizes[0] / HDIM;

    void* p;
    cudaGetSymbolAddress(&p, g_S0);
    cudaMemsetAsync(p, 0, sizeof(float) * (size_t)N_NODES * HDIM);
    cudaGetSymbolAddress(&p, g_S1);
    cudaMemsetAsync(p, 0, sizeof(float) * (size_t)N_NODES * HDIM);
    cudaGetSymbolAddress(&p, g_c0);
    cudaMemsetAsync(p, 0, sizeof(float) * N_NODES);
    cudaGetSymbolAddress(&p, g_c1);
    cudaMemsetAsync(p, 0, sizeof(float) * N_NODES);

    detect_et_kernel<<<1, 256>>>((const unsigned char*)et, E);

    {
        int threads = 256;
        long long tot = (long long)E * 16;
        int blocks = (int)((tot + threads - 1) / threads);
        scatter_kernel<<<blocks, threads>>>(feat, src, dst, et, E);
    }
    {
        size_t smem = (size_t)(16640 * 2 + 8192 + 528) * sizeof(float); // 168000 B
        cudaFuncSetAttribute(node_kernel, cudaFuncAttributeMaxDynamicSharedMemorySize, (int)smem);
        int nb = (Nn + NPB - 1) / NPB;
        node_kernel<<<nb, TPB, smem>>>(feat, W0, b0, W1, b1, Wih, Whh,
                                       bih, bhh, Wout, bout, out, Nn);
    }
}